// round 5
// baseline (speedup 1.0000x reference)
#include <cuda_runtime.h>
#include <cuda_fp16.h>
#include <cstdint>
#include <cstddef>

#define NT 256
#define SP 520   // halves per xs row: 1040B = 16B-aligned, 4B-strided 4-way, 8B 2-way

namespace {
constexpr int Bb = 2, Ss = 512, Ll = 384, CMc = 64;

struct SMem {
    __half xs[64 * SP];       // post-LN x fp16, [c][s]          66,560B
    __half2 wgh[2048];        // wg fp16 [j][colpair]             8,192B
    __half2 woh[2048];        // wo fp16                          8,192B
    float LG[8 * 512];        // logits -> attn fp32 [h][s]      16,384B
    union {
        float pbuf[2048];     // phase 2/5 partials               8,192B
        __half trow[8][512];  // phase 6 per-warp t [hc][r] fp16
    } u;
    float maskS[512];         //                                  2,048B
    float amt[512];           // a [j][h] fp32                    2,048B
    float ys[512];            // y [h][j]                         2,048B
    float qin[64];
    float qsm[64];
    float og[64];
    float red[8];
    float invD;
};
}  // namespace

__device__ __forceinline__ unsigned long long splat2(float v) {
    unsigned long long r;
    asm("mov.b64 %0, {%1, %1};" : "=l"(r) : "f"(v));
    return r;
}
__device__ __forceinline__ unsigned long long packf2(float x, float y) {
    unsigned long long r;
    asm("mov.b64 %0, {%1, %2};" : "=l"(r) : "f"(x), "f"(y));
    return r;
}
__device__ __forceinline__ void fma2(unsigned long long& d, unsigned long long a,
                                     unsigned long long b) {
    asm("fma.rn.f32x2 %0, %1, %2, %0;" : "+l"(d) : "l"(a), "l"(b));
}
__device__ __forceinline__ float2 unpk(unsigned long long v) {
    float2 f;
    asm("mov.b64 {%0, %1}, %2;" : "=f"(f.x), "=f"(f.y) : "l"(v));
    return f;
}
__device__ __forceinline__ unsigned long long h2f2(__half2 h) {
    float2 f = __half22float2(h);
    return packf2(f.x, f.y);
}
__device__ __forceinline__ float sgm(float x) { return 1.0f / (1.0f + __expf(-x)); }

__global__ void __launch_bounds__(NT, 2)
msa_col_global_attn(const float* __restrict__ m, const float* __restrict__ msa_mask,
                    const float* __restrict__ lnw, const float* __restrict__ lnb,
                    const float* __restrict__ wq, const float* __restrict__ wk,
                    const float* __restrict__ wv, const float* __restrict__ wg,
                    const float* __restrict__ bg, const float* __restrict__ wo,
                    const float* __restrict__ bo, float* __restrict__ out)
{
    extern __shared__ char smraw[];
    SMem& sm = *reinterpret_cast<SMem*>(smraw);
    const int tid = threadIdx.x;
    const int w = tid >> 5, lane = tid & 31;
    const int b = blockIdx.x / Ll, l = blockIdx.x - b * Ll;
    const size_t rowStride = (size_t)Ll * CMc;
    const float* mBase = m + ((size_t)b * Ss * Ll + l) * CMc;
    float* oBase = out + ((size_t)b * Ss * Ll + l) * CMc;

    // ---- Phase 0: mask (512) + denom partials; stage weights fp32->fp16 ----
    {
        float mk0 = msa_mask[((size_t)b * Ss + tid) * Ll + l];
        float mk1 = msa_mask[((size_t)b * Ss + tid + 256) * Ll + l];
        sm.maskS[tid] = mk0;
        sm.maskS[tid + 256] = mk1;
        float msum = mk0 + mk1;
#pragma unroll
        for (int o = 16; o; o >>= 1) msum += __shfl_xor_sync(0xffffffffu, msum, o);
        if (lane == 0) sm.red[w] = msum;
    }
    for (int idx = tid; idx < 2048; idx += NT) {
        sm.wgh[idx] = __float22half2_rn(__ldg(&reinterpret_cast<const float2*>(wg)[idx]));
        sm.woh[idx] = __float22half2_rn(__ldg(&reinterpret_cast<const float2*>(wo)[idx]));
    }

    // ---- Phase 1: LayerNorm -> xs[c][s] fp16 (warp w owns rows w*64..w*64+63) ----
    {
        const float lwA = lnw[lane], lwB = lnw[lane + 32];
        const float lbA = lnb[lane], lbB = lnb[lane + 32];
#pragma unroll 1
        for (int rr = 0; rr < 16; rr++) {
            // two row-pairs per iteration for MLP
            float a0[4], a1[4];
#pragma unroll
            for (int r = 0; r < 4; r++) {
                int s = w * 64 + rr * 4 + r;
                const float* mp = mBase + (size_t)s * rowStride;
                a0[r] = mp[lane];
                a1[r] = mp[lane + 32];
            }
            float vA[4], vB[4];
#pragma unroll
            for (int r = 0; r < 4; r++) {
                float su = a0[r] + a1[r];
                float sq = fmaf(a0[r], a0[r], a1[r] * a1[r]);
#pragma unroll
                for (int o = 16; o; o >>= 1) {
                    su += __shfl_xor_sync(0xffffffffu, su, o);
                    sq += __shfl_xor_sync(0xffffffffu, sq, o);
                }
                float mu = su * (1.0f / 64.0f);
                float var = sq * (1.0f / 64.0f) - mu * mu;
                float rs = rsqrtf(var + 1e-5f);
                vA[r] = (a0[r] - mu) * rs * lwA + lbA;
                vB[r] = (a1[r] - mu) * rs * lwB + lbB;
            }
            int s0 = w * 64 + rr * 4;
#pragma unroll
            for (int p = 0; p < 2; p++) {
                *reinterpret_cast<__half2*>(&sm.xs[lane * SP + s0 + 2 * p]) =
                    __floats2half2_rn(vA[2 * p], vA[2 * p + 1]);
                *reinterpret_cast<__half2*>(&sm.xs[(lane + 32) * SP + s0 + 2 * p]) =
                    __floats2half2_rn(vB[2 * p], vB[2 * p + 1]);
            }
        }
    }
    __syncthreads();
    if (tid == 0) {
        float s = 0.f;
#pragma unroll
        for (int i = 0; i < 8; i++) s += sm.red[i];
        sm.invD = 1.0f / fmaxf(s, 1.0f);
    }

    // ---- Phase 2: masked column sum -> qin ----
    {
        int j = tid & 63, ch = tid >> 6;  // ch covers 128 s
        const __half* xr = &sm.xs[j * SP + ch * 128];
        const float* mr = &sm.maskS[ch * 128];
        float acc = 0.f;
#pragma unroll 4
        for (int ib = 0; ib < 32; ib++) {
            __half2 xa = *reinterpret_cast<const __half2*>(xr + ib * 4);
            __half2 xb = *reinterpret_cast<const __half2*>(xr + ib * 4 + 2);
            float2 fa = __half22float2(xa), fb = __half22float2(xb);
            float4 mq = *reinterpret_cast<const float4*>(mr + ib * 4);
            acc = fmaf(fa.x, mq.x, acc);
            acc = fmaf(fa.y, mq.y, acc);
            acc = fmaf(fb.x, mq.z, acc);
            acc = fmaf(fb.y, mq.w, acc);
        }
        sm.u.pbuf[tid] = acc;
    }
    __syncthreads();
    if (tid < 64) {
        float acc = sm.u.pbuf[tid] + sm.u.pbuf[64 + tid] +
                    sm.u.pbuf[128 + tid] + sm.u.pbuf[192 + tid];
        sm.qin[tid] = acc * sm.invD;
    }
    __syncthreads();
    if (tid < 64) {
        float acc = 0.f;
#pragma unroll
        for (int j = 0; j < 64; j++) acc = fmaf(sm.qin[j], __ldg(&wq[j * 64 + tid]), acc);
        sm.qsm[tid] = acc;
    }
    __syncthreads();
    {
#pragma unroll
        for (int t2 = 0; t2 < 2; t2++) {
            int idx = 2 * tid + t2;
            int j = idx >> 3, h = idx & 7;
            float acc = 0.f;
#pragma unroll
            for (int c = 0; c < 8; c++)
                acc = fmaf(sm.qsm[h * 8 + c], __ldg(&wk[j * 64 + h * 8 + c]), acc);
            sm.amt[j * 8 + h] = acc * 0.35355339059327373f;  // 1/sqrt(C)
        }
    }
    __syncthreads();

    // ---- Phase 3: logits[h][s] = x[s]·a[h], s-pair packed f32x2 ----
    {
        const int p = tid;  // s-pair: s = 2p, 2p+1
        unsigned long long acc2[8] = {0, 0, 0, 0, 0, 0, 0, 0};
#pragma unroll 4
        for (int j = 0; j < 64; j++) {
            unsigned long long xp = h2f2(*reinterpret_cast<const __half2*>(&sm.xs[j * SP + 2 * p]));
            const float* ar = &sm.amt[j * 8];
#pragma unroll
            for (int h = 0; h < 8; h++) fma2(acc2[h], xp, splat2(ar[h]));
        }
        float mk0 = sm.maskS[2 * p], mk1 = sm.maskS[2 * p + 1];
#pragma unroll
        for (int h = 0; h < 8; h++) {
            float2 v = unpk(acc2[h]);
            sm.LG[h * 512 + 2 * p]     = (mk0 != 0.0f) ? v.x : -1e9f;
            sm.LG[h * 512 + 2 * p + 1] = (mk1 != 0.0f) ? v.y : -1e9f;
        }
    }
    __syncthreads();

    // ---- Phase 4: softmax over s; warp w owns head w entirely ----
    {
        float vals[16];
        float lm = -3.4e38f;
#pragma unroll
        for (int k = 0; k < 16; k++) {
            vals[k] = sm.LG[w * 512 + lane + k * 32];
            lm = fmaxf(lm, vals[k]);
        }
#pragma unroll
        for (int o = 16; o; o >>= 1) lm = fmaxf(lm, __shfl_xor_sync(0xffffffffu, lm, o));
        float ls = 0.f;
#pragma unroll
        for (int k = 0; k < 16; k++) {
            vals[k] = __expf(vals[k] - lm);
            ls += vals[k];
        }
#pragma unroll
        for (int o = 16; o; o >>= 1) ls += __shfl_xor_sync(0xffffffffu, ls, o);
        float inv = 1.0f / ls;
#pragma unroll
        for (int k = 0; k < 16; k++) sm.LG[w * 512 + lane + k * 32] = vals[k] * inv;
    }
    __syncthreads();

    // ---- Phase 5: y[h][j] = sum_s attn[h][s]*x[j][s], s-pair packed ----
    {
        int j = tid & 63, ch = tid >> 6;  // ch covers 64 s-pairs
        unsigned long long acc2[8] = {0, 0, 0, 0, 0, 0, 0, 0};
        const __half* xr = &sm.xs[j * SP + ch * 128];
        const float* ag = &sm.LG[ch * 128];
#pragma unroll 2
        for (int k = 0; k < 64; k++) {
            unsigned long long xp = h2f2(*reinterpret_cast<const __half2*>(xr + 2 * k));
#pragma unroll
            for (int h = 0; h < 8; h++) {
                unsigned long long ap =
                    *reinterpret_cast<const unsigned long long*>(ag + h * 512 + 2 * k);
                fma2(acc2[h], xp, ap);
            }
        }
#pragma unroll
        for (int h = 0; h < 8; h++) {
            float2 v = unpk(acc2[h]);
            sm.u.pbuf[ch * 512 + h * 64 + j] = v.x + v.y;
        }
    }
    __syncthreads();
    {
#pragma unroll
        for (int t2 = 0; t2 < 2; t2++) {
            int idx = tid + t2 * 256;
            sm.ys[idx] = sm.u.pbuf[idx] + sm.u.pbuf[512 + idx] +
                         sm.u.pbuf[1024 + idx] + sm.u.pbuf[1536 + idx];
        }
    }
    __syncthreads();
    if (tid < 64) {
        int h = tid >> 3;
        float acc = 0.f;
#pragma unroll
        for (int j = 0; j < 64; j++)
            acc = fmaf(sm.ys[h * 64 + j], __ldg(&wv[j * 64 + tid]), acc);
        sm.og[tid] = acc;
    }
    __syncthreads();

    // ---- Phase 6: out = (sigmoid(x@wg+bg)*og) @ wo + bo; 8-row blocks, f32x2 ----
    {
        const int c0 = 2 * lane;
        const float og0 = sm.og[c0], og1 = sm.og[c0 + 1];
        const float bg0 = bg[c0], bg1 = bg[c0 + 1];
        const float bo0 = bo[c0], bo1 = bo[c0 + 1];
        __half* trw = sm.u.trow[w];
#pragma unroll 1
        for (int rp = 0; rp < 8; rp++) {
            const int s0 = w * 64 + rp * 8;
            unsigned long long A[4][2];
#pragma unroll
            for (int p = 0; p < 4; p++) { A[p][0] = 0ull; A[p][1] = 0ull; }
#pragma unroll 4
            for (int j = 0; j < 64; j++) {
                uint4 raw = *reinterpret_cast<const uint4*>(&sm.xs[j * SP + s0]);  // 8 halves bc
                const __half2* hp = reinterpret_cast<const __half2*>(&raw);
                unsigned long long x0 = h2f2(hp[0]), x1 = h2f2(hp[1]);
                unsigned long long x2 = h2f2(hp[2]), x3 = h2f2(hp[3]);
                float2 wf = __half22float2(sm.wgh[j * 32 + lane]);
                unsigned long long w0 = splat2(wf.x), w1 = splat2(wf.y);
                fma2(A[0][0], x0, w0); fma2(A[0][1], x0, w1);
                fma2(A[1][0], x1, w0); fma2(A[1][1], x1, w1);
                fma2(A[2][0], x2, w0); fma2(A[2][1], x2, w1);
                fma2(A[3][0], x3, w0); fma2(A[3][1], x3, w1);
            }
            // gate epilogue -> trow[hc][r] fp16
#pragma unroll
            for (int p = 0; p < 4; p++) {
                float2 ac0 = unpk(A[p][0]);
                float2 ac1 = unpk(A[p][1]);
                float t00 = og0 * sgm(ac0.x + bg0);
                float t01 = og0 * sgm(ac0.y + bg0);
                float t10 = og1 * sgm(ac1.x + bg1);
                float t11 = og1 * sgm(ac1.y + bg1);
                *reinterpret_cast<__half2*>(&trw[c0 * 8 + 2 * p]) = __floats2half2_rn(t00, t01);
                *reinterpret_cast<__half2*>(&trw[(c0 + 1) * 8 + 2 * p]) = __floats2half2_rn(t10, t11);
            }
            __syncwarp();
            unsigned long long O[4][2];
#pragma unroll
            for (int p = 0; p < 4; p++) { O[p][0] = 0ull; O[p][1] = 0ull; }
#pragma unroll 4
            for (int hc = 0; hc < 64; hc++) {
                uint4 raw = *reinterpret_cast<const uint4*>(&trw[hc * 8]);  // 8 halves bc
                const __half2* hp = reinterpret_cast<const __half2*>(&raw);
                unsigned long long t0 = h2f2(hp[0]), t1 = h2f2(hp[1]);
                unsigned long long t2 = h2f2(hp[2]), t3 = h2f2(hp[3]);
                float2 wf = __half22float2(sm.woh[hc * 32 + lane]);
                unsigned long long w0 = splat2(wf.x), w1 = splat2(wf.y);
                fma2(O[0][0], t0, w0); fma2(O[0][1], t0, w1);
                fma2(O[1][0], t1, w0); fma2(O[1][1], t1, w1);
                fma2(O[2][0], t2, w0); fma2(O[2][1], t2, w1);
                fma2(O[3][0], t3, w0); fma2(O[3][1], t3, w1);
            }
#pragma unroll
            for (int p = 0; p < 4; p++) {
                float2 oc0 = unpk(O[p][0]);
                float2 oc1 = unpk(O[p][1]);
                int sA = s0 + 2 * p, sB = sA + 1;
                float mkA = sm.maskS[sA], mkB = sm.maskS[sB];
                *reinterpret_cast<float2*>(oBase + (size_t)sA * rowStride + c0) =
                    make_float2((oc0.x + bo0) * mkA, (oc1.x + bo1) * mkA);
                *reinterpret_cast<float2*>(oBase + (size_t)sB * rowStride + c0) =
                    make_float2((oc0.y + bo0) * mkB, (oc1.y + bo1) * mkB);
            }
            __syncwarp();
        }
    }
}

extern "C" void kernel_launch(void* const* d_in, const int* in_sizes, int n_in,
                              void* d_out, int out_size)
{
    (void)in_sizes; (void)n_in; (void)out_size;
    const float* m    = (const float*)d_in[0];
    const float* mask = (const float*)d_in[1];
    const float* lnw  = (const float*)d_in[2];
    const float* lnb  = (const float*)d_in[3];
    const float* wq   = (const float*)d_in[4];
    const float* wk   = (const float*)d_in[5];
    const float* wv   = (const float*)d_in[6];
    const float* wg   = (const float*)d_in[7];
    const float* bg   = (const float*)d_in[8];
    const float* wo   = (const float*)d_in[9];
    const float* bo   = (const float*)d_in[10];
    float* out = (float*)d_out;

    cudaFuncSetAttribute(msa_col_global_attn,
                         cudaFuncAttributeMaxDynamicSharedMemorySize,
                         (int)sizeof(SMem));
    msa_col_global_attn<<<Bb * Ll, NT, sizeof(SMem)>>>(
        m, mask, lnw, lnb, wq, wk, wv, wg, bg, wo, bo, out);
}

// round 7
// speedup vs baseline: 1.8374x; 1.8374x over previous
#include <cuda_runtime.h>
#include <cuda_fp16.h>
#include <cstdint>
#include <cstddef>

#define NT 512
#define XP 72   // halves per smem matrix row (144B: conflict-free ldmatrix, 16B-aligned)

namespace {
constexpr int Bb = 2, Ss = 512, Ll = 384, CMc = 64;

struct __align__(16) SMem {
    __half x[512 * XP];     // post-LN x fp16, row-major [s][c]      73,728B
    __half vt[512 * XP];    // v, then t                              73,728B
    __half wvg[128 * XP];   // B tile rows n: n<64 -> wv col n, else wg col n-64; cols k
    __half wot[64 * XP];    // B tile rows n: wo col n
    float LG[8 * 512];      // logits -> attn [h][s]
    float maskS[512];
    float amt[512];         // a [j][h]
    float ogP[8 * 64];      // partials (phase2 + og reduce)
    float qin[64];
    float qsm[64];
    float og[64];
    float red[16];
    float invD;
};
}  // namespace

__device__ __forceinline__ uint32_t s2u(const void* p) {
    uint32_t a;
    asm("{ .reg .u64 t; cvta.to.shared.u64 t, %1; cvt.u32.u64 %0, t; }" : "=r"(a) : "l"(p));
    return a;
}
__device__ __forceinline__ void ldmA(uint32_t* a, uint32_t addr) {
    asm volatile("ldmatrix.sync.aligned.m8n8.x4.shared.b16 {%0,%1,%2,%3}, [%4];"
                 : "=r"(a[0]), "=r"(a[1]), "=r"(a[2]), "=r"(a[3]) : "r"(addr));
}
__device__ __forceinline__ void mma16816(float* d, const uint32_t* a, const uint32_t* b) {
    asm volatile(
        "mma.sync.aligned.m16n8k16.row.col.f32.f16.f16.f32 "
        "{%0,%1,%2,%3}, {%4,%5,%6,%7}, {%8,%9}, {%0,%1,%2,%3};"
        : "+f"(d[0]), "+f"(d[1]), "+f"(d[2]), "+f"(d[3])
        : "r"(a[0]), "r"(a[1]), "r"(a[2]), "r"(a[3]), "r"(b[0]), "r"(b[1]));
}
__device__ __forceinline__ float sgm(float x) { return 1.0f / (1.0f + __expf(-x)); }

__global__ void __launch_bounds__(NT, 1)
msa_col_global_attn(const float* __restrict__ m, const float* __restrict__ msa_mask,
                    const float* __restrict__ lnw, const float* __restrict__ lnb,
                    const float* __restrict__ wq, const float* __restrict__ wk,
                    const float* __restrict__ wv, const float* __restrict__ wg,
                    const float* __restrict__ bg, const float* __restrict__ wo,
                    const float* __restrict__ bo, float* __restrict__ out)
{
    extern __shared__ __align__(16) char smraw[];
    SMem& sm = *reinterpret_cast<SMem*>(smraw);
    const int tid = threadIdx.x;
    const int w = tid >> 5, lane = tid & 31;
    const int mw = w >> 2, nw = w & 3;   // warp tile coords for GEMM passes
    const int b = blockIdx.x / Ll, l = blockIdx.x - b * Ll;
    const size_t rowStride = (size_t)Ll * CMc;
    const float* mBase = m + ((size_t)b * Ss * Ll + l) * CMc;
    float* oBase = out + ((size_t)b * Ss * Ll + l) * CMc;

    // ---- Phase 0: mask + denom partials; weight staging; LayerNorm ----
    {
        float mk = msa_mask[((size_t)b * Ss + tid) * Ll + l];
        sm.maskS[tid] = mk;
        float ms = mk;
#pragma unroll
        for (int o = 16; o; o >>= 1) ms += __shfl_xor_sync(0xffffffffu, ms, o);
        if (lane == 0) sm.red[w] = ms;
    }
    for (int idx = tid; idx < 8192; idx += NT) {
        int n = idx & 127, k = idx >> 7;
        float v = (n < 64) ? __ldg(&wv[k * 64 + n]) : __ldg(&wg[k * 64 + (n - 64)]);
        sm.wvg[n * XP + k] = __float2half(v);
    }
    for (int idx = tid; idx < 4096; idx += NT) {
        int n = idx & 63, k = idx >> 6;
        sm.wot[n * XP + k] = __float2half(__ldg(&wo[k * 64 + n]));
    }
    {
        const float lwA = lnw[lane], lwB = lnw[lane + 32];
        const float lbA = lnb[lane], lbB = lnb[lane + 32];
#pragma unroll 1
        for (int rb = 0; rb < 4; rb++) {
            float a0[8], a1[8];
#pragma unroll
            for (int r = 0; r < 8; r++) {
                int s = w * 32 + rb * 8 + r;
                const float* mp = mBase + (size_t)s * rowStride;
                a0[r] = mp[lane];
                a1[r] = mp[lane + 32];
            }
#pragma unroll
            for (int r = 0; r < 8; r++) {
                int s = w * 32 + rb * 8 + r;
                float su = a0[r] + a1[r];
                float sq = fmaf(a0[r], a0[r], a1[r] * a1[r]);
#pragma unroll
                for (int o = 16; o; o >>= 1) {
                    su += __shfl_xor_sync(0xffffffffu, su, o);
                    sq += __shfl_xor_sync(0xffffffffu, sq, o);
                }
                float mu = su * (1.0f / 64.0f);
                float var = sq * (1.0f / 64.0f) - mu * mu;
                float rs = rsqrtf(var + 1e-5f);
                sm.x[s * XP + lane]      = __float2half((a0[r] - mu) * rs * lwA + lbA);
                sm.x[s * XP + lane + 32] = __float2half((a1[r] - mu) * rs * lwB + lbB);
            }
        }
    }
    __syncthreads();  // S1: x, weights, mask ready
    if (tid == 0) {
        float s = 0.f;
#pragma unroll
        for (int i = 0; i < 16; i++) s += sm.red[i];
        sm.invD = 1.0f / fmaxf(s, 1.0f);
    }

    // ---- Phase 2: masked column sum -> qin -> q -> a[j][h] ----
    {
        int c = tid & 63, sc = tid >> 6;
        float acc = 0.f;
#pragma unroll 8
        for (int i = 0; i < 64; i++) {
            int s = sc * 64 + i;
            acc = fmaf(__half2float(sm.x[s * XP + c]), sm.maskS[s], acc);
        }
        sm.ogP[sc * 64 + c] = acc;
    }
    __syncthreads();  // S2
    if (tid < 64) {
        float acc = 0.f;
#pragma unroll
        for (int sc = 0; sc < 8; sc++) acc += sm.ogP[sc * 64 + tid];
        sm.qin[tid] = acc * sm.invD;
    }
    __syncthreads();  // S3
    if (tid < 64) {
        float acc = 0.f;
#pragma unroll
        for (int j = 0; j < 64; j++) acc = fmaf(sm.qin[j], __ldg(&wq[j * 64 + tid]), acc);
        sm.qsm[tid] = acc;
    }
    __syncthreads();  // S4
    {
        int j = tid >> 3, h = tid & 7;
        float acc = 0.f;
#pragma unroll
        for (int c = 0; c < 8; c++)
            acc = fmaf(sm.qsm[h * 8 + c], __ldg(&wk[j * 64 + h * 8 + c]), acc);
        sm.amt[j * 8 + h] = acc * 0.35355339059327373f;  // 1/sqrt(C)
    }
    __syncthreads();  // S5

    // ---- Phase 3: logits[h][s] = x[s]·a[h], masked ----
    {
        int s = tid;
        uint4 raw[8];
#pragma unroll
        for (int q = 0; q < 8; q++)
            raw[q] = *reinterpret_cast<const uint4*>(&sm.x[s * XP + q * 8]);
        const __half* xr = reinterpret_cast<const __half*>(raw);
        float acc[8] = {0, 0, 0, 0, 0, 0, 0, 0};
#pragma unroll
        for (int j = 0; j < 64; j++) {
            float xv = __half2float(xr[j]);
            const float4* ap = reinterpret_cast<const float4*>(&sm.amt[j * 8]);
            float4 q0 = ap[0], q1 = ap[1];
            acc[0] = fmaf(xv, q0.x, acc[0]); acc[1] = fmaf(xv, q0.y, acc[1]);
            acc[2] = fmaf(xv, q0.z, acc[2]); acc[3] = fmaf(xv, q0.w, acc[3]);
            acc[4] = fmaf(xv, q1.x, acc[4]); acc[5] = fmaf(xv, q1.y, acc[5]);
            acc[6] = fmaf(xv, q1.z, acc[6]); acc[7] = fmaf(xv, q1.w, acc[7]);
        }
        float mk = sm.maskS[s];
#pragma unroll
        for (int h = 0; h < 8; h++) sm.LG[h * 512 + s] = (mk != 0.0f) ? acc[h] : -1e9f;
    }
    __syncthreads();  // S6

    // ---- Phase 4: softmax, warp w<8 owns head w ----
    if (w < 8) {
        float vals[16];
        float lm = -3.4e38f;
#pragma unroll
        for (int k = 0; k < 16; k++) {
            vals[k] = sm.LG[w * 512 + lane + k * 32];
            lm = fmaxf(lm, vals[k]);
        }
#pragma unroll
        for (int o = 16; o; o >>= 1) lm = fmaxf(lm, __shfl_xor_sync(0xffffffffu, lm, o));
        float ls = 0.f;
#pragma unroll
        for (int k = 0; k < 16; k++) {
            vals[k] = __expf(vals[k] - lm);
            ls += vals[k];
        }
#pragma unroll
        for (int o = 16; o; o >>= 1) ls += __shfl_xor_sync(0xffffffffu, ls, o);
        float inv = 1.0f / ls;
#pragma unroll
        for (int k = 0; k < 16; k++) sm.LG[w * 512 + lane + k * 32] = vals[k] * inv;
    }
    __syncthreads();  // S7

    // ---- Pass V: v = x @ wv  (warp: 128 rows x 16 cols), v -> vt fp16 ----
    {
        uint32_t B[2][4][2];
#pragma unroll
        for (int nt = 0; nt < 2; nt++)
#pragma unroll
            for (int kt = 0; kt < 4; kt++) {
                int row = nw * 16 + nt * 8 + (lane >> 2);
                int col = kt * 16 + (lane & 3) * 2;
                B[nt][kt][0] = *reinterpret_cast<const uint32_t*>(&sm.wvg[row * XP + col]);
                B[nt][kt][1] = *reinterpret_cast<const uint32_t*>(&sm.wvg[row * XP + col + 8]);
            }
#pragma unroll 1
        for (int mt = 0; mt < 8; mt++) {
            int s0 = mw * 128 + mt * 16;
            uint32_t A[4][4];
#pragma unroll
            for (int kt = 0; kt < 4; kt++)
                ldmA(A[kt], s2u(&sm.x[(s0 + (lane & 15)) * XP + kt * 16 + ((lane >> 4) << 3)]));
            float acc[2][4] = {{0, 0, 0, 0}, {0, 0, 0, 0}};
#pragma unroll
            for (int kt = 0; kt < 4; kt++)
#pragma unroll
                for (int nt = 0; nt < 2; nt++) mma16816(acc[nt], A[kt], B[nt][kt]);
            int r = s0 + (lane >> 2), c = nw * 16 + (lane & 3) * 2;
#pragma unroll
            for (int nt = 0; nt < 2; nt++) {
                *reinterpret_cast<__half2*>(&sm.vt[r * XP + c + nt * 8]) =
                    __floats2half2_rn(acc[nt][0], acc[nt][1]);
                *reinterpret_cast<__half2*>(&sm.vt[(r + 8) * XP + c + nt * 8]) =
                    __floats2half2_rn(acc[nt][2], acc[nt][3]);
            }
        }
    }
    __syncthreads();  // S8: v ready

    // ---- og[hc] = sum_s attn[hc>>3][s] * v[s][hc] ----
    {
        int hc = tid & 63, ck = tid >> 6;
        const float* ar = &sm.LG[(hc >> 3) * 512 + ck * 64];
        float acc = 0.f;
#pragma unroll 8
        for (int i = 0; i < 64; i++)
            acc = fmaf(ar[i], __half2float(sm.vt[(ck * 64 + i) * XP + hc]), acc);
        sm.ogP[ck * 64 + hc] = acc;
    }
    __syncthreads();  // S9
    if (tid < 64) {
        float acc = 0.f;
#pragma unroll
        for (int ck = 0; ck < 8; ck++) acc += sm.ogP[ck * 64 + tid];
        sm.og[tid] = acc;
    }
    __syncthreads();  // S10

    // ---- Pass G: t = og * sigmoid(x @ wg + bg) -> vt (overwrite) ----
    {
        uint32_t B[2][4][2];
#pragma unroll
        for (int nt = 0; nt < 2; nt++)
#pragma unroll
            for (int kt = 0; kt < 4; kt++) {
                int row = 64 + nw * 16 + nt * 8 + (lane >> 2);
                int col = kt * 16 + (lane & 3) * 2;
                B[nt][kt][0] = *reinterpret_cast<const uint32_t*>(&sm.wvg[row * XP + col]);
                B[nt][kt][1] = *reinterpret_cast<const uint32_t*>(&sm.wvg[row * XP + col + 8]);
            }
        int cbase = nw * 16 + (lane & 3) * 2;
        float og0[2], og1[2], bg0[2], bg1[2];
#pragma unroll
        for (int nt = 0; nt < 2; nt++) {
            og0[nt] = sm.og[cbase + nt * 8];
            og1[nt] = sm.og[cbase + nt * 8 + 1];
            bg0[nt] = __ldg(&bg[cbase + nt * 8]);
            bg1[nt] = __ldg(&bg[cbase + nt * 8 + 1]);
        }
#pragma unroll 1
        for (int mt = 0; mt < 8; mt++) {
            int s0 = mw * 128 + mt * 16;
            uint32_t A[4][4];
#pragma unroll
            for (int kt = 0; kt < 4; kt++)
                ldmA(A[kt], s2u(&sm.x[(s0 + (lane & 15)) * XP + kt * 16 + ((lane >> 4) << 3)]));
            float acc[2][4] = {{0, 0, 0, 0}, {0, 0, 0, 0}};
#pragma unroll
            for (int kt = 0; kt < 4; kt++)
#pragma unroll
                for (int nt = 0; nt < 2; nt++) mma16816(acc[nt], A[kt], B[nt][kt]);
            int r = s0 + (lane >> 2);
#pragma unroll
            for (int nt = 0; nt < 2; nt++) {
                float t0 = og0[nt] * sgm(acc[nt][0] + bg0[nt]);
                float t1 = og1[nt] * sgm(acc[nt][1] + bg1[nt]);
                float t2 = og0[nt] * sgm(acc[nt][2] + bg0[nt]);
                float t3 = og1[nt] * sgm(acc[nt][3] + bg1[nt]);
                *reinterpret_cast<__half2*>(&sm.vt[r * XP + cbase + nt * 8]) =
                    __floats2half2_rn(t0, t1);
                *reinterpret_cast<__half2*>(&sm.vt[(r + 8) * XP + cbase + nt * 8]) =
                    __floats2half2_rn(t2, t3);
            }
        }
    }
    __syncthreads();  // S11: t ready

    // ---- Pass O: out = (t @ wo + bo) * mask -> global (direct from D frags) ----
    {
        uint32_t B[2][4][2];
#pragma unroll
        for (int nt = 0; nt < 2; nt++)
#pragma unroll
            for (int kt = 0; kt < 4; kt++) {
                int row = nw * 16 + nt * 8 + (lane >> 2);
                int col = kt * 16 + (lane & 3) * 2;
                B[nt][kt][0] = *reinterpret_cast<const uint32_t*>(&sm.wot[row * XP + col]);
                B[nt][kt][1] = *reinterpret_cast<const uint32_t*>(&sm.wot[row * XP + col + 8]);
            }
        int cbase = nw * 16 + (lane & 3) * 2;
        float bo0[2], bo1[2];
#pragma unroll
        for (int nt = 0; nt < 2; nt++) {
            bo0[nt] = __ldg(&bo[cbase + nt * 8]);
            bo1[nt] = __ldg(&bo[cbase + nt * 8 + 1]);
        }
#pragma unroll 1
        for (int mt = 0; mt < 8; mt++) {
            int s0 = mw * 128 + mt * 16;
            uint32_t A[4][4];
#pragma unroll
            for (int kt = 0; kt < 4; kt++)
                ldmA(A[kt], s2u(&sm.vt[(s0 + (lane & 15)) * XP + kt * 16 + ((lane >> 4) << 3)]));
            float acc[2][4] = {{0, 0, 0, 0}, {0, 0, 0, 0}};
#pragma unroll
            for (int kt = 0; kt < 4; kt++)
#pragma unroll
                for (int nt = 0; nt < 2; nt++) mma16816(acc[nt], A[kt], B[nt][kt]);
            int r = s0 + (lane >> 2);
            float mkA = sm.maskS[r], mkB = sm.maskS[r + 8];
#pragma unroll
            for (int nt = 0; nt < 2; nt++) {
                *reinterpret_cast<float2*>(oBase + (size_t)r * rowStride + cbase + nt * 8) =
                    make_float2((acc[nt][0] + bo0[nt]) * mkA, (acc[nt][1] + bo1[nt]) * mkA);
                *reinterpret_cast<float2*>(oBase + (size_t)(r + 8) * rowStride + cbase + nt * 8) =
                    make_float2((acc[nt][2] + bo0[nt]) * mkB, (acc[nt][3] + bo1[nt]) * mkB);
            }
        }
    }
}

extern "C" void kernel_launch(void* const* d_in, const int* in_sizes, int n_in,
                              void* d_out, int out_size)
{
    (void)in_sizes; (void)n_in; (void)out_size;
    const float* m    = (const float*)d_in[0];
    const float* mask = (const float*)d_in[1];
    const float* lnw  = (const float*)d_in[2];
    const float* lnb  = (const float*)d_in[3];
    const float* wq   = (const float*)d_in[4];
    const float* wk   = (const float*)d_in[5];
    const float* wv   = (const float*)d_in[6];
    const float* wg   = (const float*)d_in[7];
    const float* bg   = (const float*)d_in[8];
    const float* wo   = (const float*)d_in[9];
    const float* bo   = (const float*)d_in[10];
    float* out = (float*)d_out;

    cudaFuncSetAttribute(msa_col_global_attn,
                         cudaFuncAttributeMaxDynamicSharedMemorySize,
                         (int)sizeof(SMem));
    msa_col_global_attn<<<Bb * Ll, NT, sizeof(SMem)>>>(
        m, mask, lnw, lnb, wq, wk, wv, wg, bg, wo, bo, out);
}